// round 13
// baseline (speedup 1.0000x reference)
#include <cuda_runtime.h>
#include <math.h>

// grid_layer, two kernels.
//  K1: per-(node,neighbor) great-circle (dist,phi). Fast __sincosf + precise
//      acosf/atan2f, separately-rounded products. Self-pair degeneracy still
//      exact: identical inputs -> s1==s2,c1==c2 -> yy=+0, sd=+0 ->
//      atan2(+0,+0)=+0 (bit-matches XLA; FMA contraction here was the old
//      sqrt(1/7) bug).
//  K2: one warp per TWO nodes. All per-node inputs loaded cooperatively and
//      front-batched (MLP), broadcast via smem LDS (conflict-free) and shfl;
//      compute/store serialized per node to cap registers. Per-node L1
//      wavefronts are at the structural floor (16 STG + 28 LDS + ~9 LDG).

#define PI_F 3.14159265358979323846f
#define FULL 0xffffffffu
#define MAXN 65536

__device__ float2 g_dp[MAXN * 7];   // (dist, phi) per (node, neighbor)

// ---------------- Kernel 1: trig, one thread per (node, k) ------------------
__global__ __launch_bounds__(256) void trig_kernel(
    const float* __restrict__ coords,      // [2, N]
    const int*   __restrict__ local_indices,
    const int*   __restrict__ adjc,        // [N, 7]
    int N)
{
    const int t = blockIdx.x * 256 + threadIdx.x;
    if (t >= N * 7) return;
    const int node = t / 7;
    const int k    = t - node * 7;

    const int li   = __ldg(&local_indices[node]);
    const int idx0 = __ldg(&adjc[li * 7]);
    const int idxk = __ldg(&adjc[li * 7 + k]);

    const float lon1 = __ldg(&coords[idx0]);
    const float lat1 = __ldg(&coords[N + idx0]);
    const float lon2 = __ldg(&coords[idxk]);
    const float lat2 = __ldg(&coords[N + idxk]);
    const float dlon = lon2 - lon1;

    float s1, c1, s2, c2, sd, cd;
    __sincosf(lat1, &s1, &c1);
    __sincosf(lat2, &s2, &c2);
    __sincosf(dlon, &sd, &cd);

    // separately rounded products (degenerate case must give exact +0)
    float cosd = __fadd_rn(__fmul_rn(s1, s2),
                           __fmul_rn(__fmul_rn(c1, c2), cd));
    cosd = fminf(fmaxf(cosd, -1.0f + 1e-7f), 1.0f - 1e-7f);

    const float yy = __fsub_rn(__fmul_rn(c1, s2),
                               __fmul_rn(__fmul_rn(s1, c2), cd));
    const float xx = __fmul_rn(sd, c2);

    g_dp[t] = make_float2(acosf(cosd), atan2f(xx, yy));
}

// ---------------- Kernel 2: weights + gather + store, 2 nodes per warp ------
__global__ __launch_bounds__(256) void project_kernel(
    const float* __restrict__ x,
    const float* __restrict__ sigma_d_p,
    const float* __restrict__ kappa_p,
    const int*   __restrict__ local_indices,
    const int*   __restrict__ adjc,
    float*       __restrict__ out,         // [N, 4, 8, 16]
    int N)
{
    __shared__ float xs[8][2][116];        // per warp: 2 nodes x (7x16 feats)

    const int warp = threadIdx.x >> 5;
    const int lane = threadIdx.x & 31;
    const int n0 = (blockIdx.x * 8 + warp) * 2;
    const int n1 = n0 + 1;
    if (n0 >= N) return;
    const bool has1 = (n1 < N);

    // ---- front-batched loads (maximize outstanding loads) ----
    // adjc (speculate li == node): lanes 0..6 -> n0, lanes 16..22 -> n1
    const int sub  = lane >> 4;            // 0: node0 half, 1: node1 half
    const int sl   = lane & 15;
    const int nsub = sub ? n1 : n0;
    int idxk = 0;
    if (sl < 7 && (sub == 0 || has1))
        idxk = __ldg(&adjc[nsub * 7 + sl]);

    // dp: lanes 0..13 -> n0's 14 floats, lanes 16..29 -> n1's
    float dpv = 0.0f;
    if (sl < 14 && (sub == 0 || has1))
        dpv = __ldg(reinterpret_cast<const float*>(g_dp) + nsub * 14 + sl);

    // local_indices check (rarely diverges from node id)
    int liv = 0;
    if (sl == 15) liv = __ldg(&local_indices[nsub]);
    const int li0 = __shfl_sync(FULL, liv, 15);
    const int li1 = __shfl_sync(FULL, liv, 31);
    if (li0 != n0 && sub == 0 && sl < 7)
        idxk = __ldg(&adjc[li0 * 7 + sl]);
    if (has1 && li1 != n1 && sub == 1 && sl < 7)
        idxk = __ldg(&adjc[li1 * 7 + sl]);

    // x rows: 28 chunks per node, 1-2 LDG.128 per lane
    {
        const int xi0 = __shfl_sync(FULL, idxk, lane >> 2);         // n0 rows
        const int xi1 = __shfl_sync(FULL, idxk, 16 + (lane >> 2));  // n1 rows
        float4 v0, v1;
        if (lane < 28)
            v0 = __ldg(reinterpret_cast<const float4*>(x + xi0 * 16) + (lane & 3));
        if (lane < 28 && has1)
            v1 = __ldg(reinterpret_cast<const float4*>(x + xi1 * 16) + (lane & 3));
        if (lane < 28) {
            const int off = (lane >> 2) * 16 + (lane & 3) * 4;
            *reinterpret_cast<float4*>(&xs[warp][0][off]) = v0;
            if (has1) *reinterpret_cast<float4*>(&xs[warp][1][off]) = v1;
        }
    }
    __syncwarp();

    // ---- broadcast dist/phi to every lane (both nodes) ----
    float dist0[7], phi0[7], dist1[7], phi1[7];
#pragma unroll
    for (int k = 0; k < 7; k++) {
        dist0[k] = __shfl_sync(FULL, dpv, 2 * k);
        phi0[k]  = __shfl_sync(FULL, dpv, 2 * k + 1);
        dist1[k] = __shfl_sync(FULL, dpv, 16 + 2 * k);
        phi1[k]  = __shfl_sync(FULL, dpv, 16 + 2 * k + 1);
    }

    const float inv_sigma = 1.0f / __ldg(&sigma_d_p[0]);
    const float kappa     = __ldg(&kappa_p[0]);

    // this lane's (d, t) grid cell
    const float dpos  = (float)(lane >> 3) * (0.2f / 3.0f);
    const float theta = -PI_F + (float)(lane & 7) * (PI_F * 0.25f);

    // ---- node0: weights, weighted sum, store ----
#pragma unroll
    for (int nn = 0; nn < 2; nn++) {
        if (nn == 1 && !has1) break;
        const float* dist = (nn == 0) ? dist0 : dist1;
        const float* phi  = (nn == 0) ? phi0  : phi1;

        float w[7];
        float sum = 0.0f;
#pragma unroll
        for (int k = 0; k < 7; k++) {
            const float z   = (dpos - dist[k]) * inv_sigma;
            const float arg = __fmaf_rn(kappa, __cosf(theta - phi[k]),
                                        -0.5f * z * z);
            w[k] = __expf(arg);
            sum += w[k];
        }
        const float inv = 1.0f / (sum + 1e-10f);

        float4 a0 = make_float4(0.f, 0.f, 0.f, 0.f);
        float4 a1 = a0, a2 = a0, a3 = a0;
        const float* xw = xs[warp][nn];
#pragma unroll
        for (int k = 0; k < 7; k++) {
            const float wk = w[k] * inv;
            const float4 v0 = *reinterpret_cast<const float4*>(xw + k * 16 + 0);
            const float4 v1 = *reinterpret_cast<const float4*>(xw + k * 16 + 4);
            const float4 v2 = *reinterpret_cast<const float4*>(xw + k * 16 + 8);
            const float4 v3 = *reinterpret_cast<const float4*>(xw + k * 16 + 12);
            a0.x += wk * v0.x; a0.y += wk * v0.y; a0.z += wk * v0.z; a0.w += wk * v0.w;
            a1.x += wk * v1.x; a1.y += wk * v1.y; a1.z += wk * v1.z; a1.w += wk * v1.w;
            a2.x += wk * v2.x; a2.y += wk * v2.y; a2.z += wk * v2.z; a2.w += wk * v2.w;
            a3.x += wk * v3.x; a3.y += wk * v3.y; a3.z += wk * v3.z; a3.w += wk * v3.w;
        }

        float* o = out + (n0 + nn) * 512 + lane * 16;
        reinterpret_cast<float4*>(o)[0] = a0;
        reinterpret_cast<float4*>(o)[1] = a1;
        reinterpret_cast<float4*>(o)[2] = a2;
        reinterpret_cast<float4*>(o)[3] = a3;
    }
}

extern "C" void kernel_launch(void* const* d_in, const int* in_sizes, int n_in,
                              void* d_out, int out_size) {
    const int N = out_size / 512;   // out is (1, N, 4, 8, 16)

    // Bind inputs by element count (robust to metadata ordering).
    const float* x       = 0;
    const float* coords  = 0;
    const float* sigma_d = 0;
    const float* kappa   = 0;
    const int*   lidx    = 0;
    const int*   adjc    = 0;
    int n_scalar = 0;
    for (int i = 0; i < n_in; i++) {
        const int s = in_sizes[i];
        if (s == 1) {
            if (n_scalar++ == 0) sigma_d = (const float*)d_in[i];
            else                 kappa   = (const float*)d_in[i];
        } else if (s == N)        lidx   = (const int*)d_in[i];
        else if (s == 2 * N)      coords = (const float*)d_in[i];
        else if (s == 7 * N)      adjc   = (const int*)d_in[i];
        else if (s == 16 * N)     x      = (const float*)d_in[i];
    }

    float* out = (float*)d_out;

    const int t1 = N * 7;
    trig_kernel<<<(t1 + 255) / 256, 256>>>(coords, lidx, adjc, N);
    const int nodes_per_block = 16;                  // 8 warps x 2 nodes
    project_kernel<<<(N + nodes_per_block - 1) / nodes_per_block, 256>>>(
        x, sigma_d, kappa, lidx, adjc, out, N);
}